// round 11
// baseline (speedup 1.0000x reference)
#include <cuda_runtime.h>
#include <cuda_fp16.h>
#include <mma.h>
#include <math.h>

using namespace nvcuda;

constexpr int NN   = 50000;
constexpr int EE   = 800000;
constexpr int DIN  = 128;
constexpr int DE   = 16;
constexpr int C    = 64;
constexpr int HID  = 256;
constexpr float NEG = 0.2f;

constexpr int SCAT_BLOCKS = (EE + 255) / 256;        // 3125
constexpr int ROW_BLOCKS  = (NN + 63) / 64;          // 782
constexpr int EWE_BLOCKS  = (EE + 63) / 64;          // 12500

// ---------------- device scratch --------------------------------------------
__device__ int    g_cnt[NN];          // zero at load; re-zeroed by scan each run
__device__ int    g_rowptr[NN + 1];
__device__ int    g_cursor[NN];
__device__ int2   g_csr_se[EE];       // (src, eid) per CSR slot
__device__ __half g_ewe1[(size_t)EE * 64];   // layer-1 e@We, fp16
__device__ __half g_ewe2[(size_t)EE * 64];   // layer-2 e@We, fp16
__device__ float  g_xlr[NN * 128];    // cols 0..63 = xl, 64..127 = xr
__device__ float  g_h[NN * C];
__device__ float  g_h2[NN * C];
__device__ float  g_P12[NN * 512];    // cols 0..255 = P1, 256..511 = P2
__device__ float  g_Wp1[DIN * 128];
__device__ float  g_Wp2[C * 128];
__device__ float  g_WpC[C * 512];
__device__ float  g_Wep[DE * 128];    // [We1 | We2]
__device__ float  g_bp1[128];
__device__ float  g_bp2[128];

__device__ __forceinline__ float lrelu(float x) { return x > 0.f ? x : NEG * x; }
__device__ __forceinline__ float eluf(float x)  { return x > 0.f ? x : __expf(x) - 1.f; }

typedef unsigned long long ull;
__device__ __forceinline__ ull pack2(float lo, float hi) {
    ull r;
    asm("mov.b64 %0, {%1, %2};" : "=l"(r) : "f"(lo), "f"(hi));
    return r;
}
__device__ __forceinline__ void unpack2(ull v, float& lo, float& hi) {
    asm("mov.b64 {%0, %1}, %2;" : "=f"(lo), "=f"(hi) : "l"(v));
}
__device__ __forceinline__ ull ffma2(ull a, ull b, ull c) {
    ull d;
    asm("fma.rn.f32x2 %0, %1, %2, %3;" : "=l"(d) : "l"(a), "l"(b), "l"(c));
    return d;
}
__device__ __forceinline__ ull add2(ull a, ull b) {
    ull d;
    asm("add.rn.f32x2 %0, %1, %2;" : "=l"(d) : "l"(a), "l"(b));
    return d;
}
__device__ __forceinline__ ull mul2(ull a, ull b) {
    ull d;
    asm("mul.rn.f32x2 %0, %1, %2;" : "=l"(d) : "l"(a), "l"(b));
    return d;
}

// ---------------- launch 1: pack weights + degree histogram ------------------
__global__ void prep_kernel(const float* __restrict__ W1l, const float* __restrict__ W1r,
                            const float* __restrict__ b1l, const float* __restrict__ b1r,
                            const float* __restrict__ W2l, const float* __restrict__ W2r,
                            const float* __restrict__ b2l, const float* __restrict__ b2r,
                            const float* __restrict__ We1, const float* __restrict__ We2,
                            const float* __restrict__ Cw1,
                            const int* __restrict__ ei) {
    int i = blockIdx.x * blockDim.x + threadIdx.x;
    if (i < EE) atomicAdd(&g_cnt[ei[EE + i]], 1);   // g_cnt zeroed by prior scan
    if (i < DIN * 128) {
        int k = i >> 7, c = i & 127;
        g_Wp1[i] = (c < 64) ? W1l[k * 64 + c] : W1r[k * 64 + c - 64];
    }
    if (i < DE * 128) {
        int k = i >> 7, c = i & 127;
        g_Wep[i] = (c < 64) ? We1[k * 64 + c] : We2[k * 64 + c - 64];
    }
    int j = i - DIN * 128;
    if (j >= 0 && j < C * 128) {
        int k = j >> 7, c = j & 127;
        g_Wp2[j] = (c < 64) ? W2l[k * 64 + c] : W2r[k * 64 + c - 64];
    }
    int l = i - DIN * 128 - C * 128;
    if (l >= 0 && l < C * 512) {
        int k = l >> 9, c = l & 511;
        g_WpC[l] = (c < 256) ? Cw1[k * 256 + c] : Cw1[(64 + k) * 256 + c - 256];
    }
    if (i < 128) {
        g_bp1[i] = (i < 64) ? b1l[i] : b1r[i - 64];
        g_bp2[i] = (i < 64) ? b2l[i] : b2r[i - 64];
    }
}

// ---------------- launch 2: scan (and re-zero g_cnt for the next run) --------
__global__ void csr_scan_kernel() {
    __shared__ int wsum[32];
    int t = threadIdx.x, lane = t & 31, wid = t >> 5;
    int running = 0;
    const int CH = (NN + 1023) / 1024;
    for (int c = 0; c < CH; c++) {
        int i = c * 1024 + t;
        int v = 0;
        if (i < NN) { v = g_cnt[i]; g_cnt[i] = 0; }
        int s = v;
        #pragma unroll
        for (int o = 1; o < 32; o <<= 1) {
            int u = __shfl_up_sync(0xffffffffu, s, o);
            if (lane >= o) s += u;
        }
        if (lane == 31) wsum[wid] = s;
        __syncthreads();
        if (wid == 0) {
            int ws = wsum[lane];
            #pragma unroll
            for (int o = 1; o < 32; o <<= 1) {
                int u = __shfl_up_sync(0xffffffffu, ws, o);
                if (lane >= o) ws += u;
            }
            wsum[lane] = ws;
        }
        __syncthreads();
        int excl = running + (wid ? wsum[wid - 1] : 0) + s - v;
        if (i < NN) { g_rowptr[i] = excl; g_cursor[i] = excl; }
        running += wsum[31];
        __syncthreads();
    }
    if (t == 0) g_rowptr[NN] = running;
}

// ---------------- tf32 WMMA GEMM body ----------------------------------------
constexpr int LDA = 40;
constexpr int LDB = 72;
constexpr int LDO = 72;
constexpr int LDA2 = 24;   // ewe A tile: 16 + 8 pad

constexpr int SM_GEMM  = 64 * LDA + 32 * LDB;                 // 4864
constexpr int SM_EWE   = 64 * LDA2 + 16 * LDB + 64 * LDO;     // 7296
constexpr int SM_FUSED = (SM_GEMM > SM_EWE) ? SM_GEMM : SM_EWE;

__device__ void gemm_body(float* sm,
                          const float* __restrict__ X,
                          const float* __restrict__ W,
                          const float* __restrict__ bias,
                          float* __restrict__ Cmat,
                          int n, int K, int Cout,
                          int rowTile, int colTile) {
    float* As = sm;
    float* Bs = sm + 64 * LDA;
    float* sOut = sm;

    int tid = threadIdx.x;
    int warpId = tid >> 5;
    int rowBase = rowTile * 64;
    int colB    = colTile * 64;
    int warpRow = (warpId & 3) * 16;
    int warpCol = (warpId >> 2) * 32;

    wmma::fragment<wmma::accumulator, 16, 16, 8, float> acc0, acc1;
    wmma::fill_fragment(acc0, 0.f);
    wmma::fill_fragment(acc1, 0.f);

    for (int kt = 0; kt < K; kt += 32) {
        #pragma unroll
        for (int f = tid; f < 512; f += 256) {
            int row = f >> 3, kq = f & 7;
            float4 v = make_float4(0.f, 0.f, 0.f, 0.f);
            if (rowBase + row < n)
                v = *(const float4*)&X[(size_t)(rowBase + row) * K + kt + kq * 4];
            float* d = &As[row * LDA + kq * 4];
            d[0] = wmma::__float_to_tf32(v.x);
            d[1] = wmma::__float_to_tf32(v.y);
            d[2] = wmma::__float_to_tf32(v.z);
            d[3] = wmma::__float_to_tf32(v.w);
        }
        #pragma unroll
        for (int f = tid; f < 512; f += 256) {
            int row = f >> 4, cq = f & 15;
            float4 v = *(const float4*)&W[(size_t)(kt + row) * Cout + colB + cq * 4];
            float* d = &Bs[row * LDB + cq * 4];
            d[0] = wmma::__float_to_tf32(v.x);
            d[1] = wmma::__float_to_tf32(v.y);
            d[2] = wmma::__float_to_tf32(v.z);
            d[3] = wmma::__float_to_tf32(v.w);
        }
        __syncthreads();
        #pragma unroll
        for (int kk = 0; kk < 32; kk += 8) {
            wmma::fragment<wmma::matrix_a, 16, 16, 8, wmma::precision::tf32, wmma::row_major> a;
            wmma::fragment<wmma::matrix_b, 16, 16, 8, wmma::precision::tf32, wmma::row_major> b0, b1;
            wmma::load_matrix_sync(a, &As[warpRow * LDA + kk], LDA);
            wmma::load_matrix_sync(b0, &Bs[kk * LDB + warpCol], LDB);
            wmma::load_matrix_sync(b1, &Bs[kk * LDB + warpCol + 16], LDB);
            wmma::mma_sync(acc0, a, b0, acc0);
            wmma::mma_sync(acc1, a, b1, acc1);
        }
        __syncthreads();
    }

    wmma::store_matrix_sync(&sOut[warpRow * LDO + warpCol],      acc0, LDO, wmma::mem_row_major);
    wmma::store_matrix_sync(&sOut[warpRow * LDO + warpCol + 16], acc1, LDO, wmma::mem_row_major);
    __syncthreads();
    #pragma unroll
    for (int f = tid; f < 1024; f += 256) {
        int row = f >> 4, cq = f & 15;
        if (rowBase + row < n) {
            float4 v = *(float4*)&sOut[row * LDO + cq * 4];
            if (bias) {
                float4 b = *(const float4*)&bias[colB + cq * 4];
                v.x += b.x; v.y += b.y; v.z += b.z; v.w += b.w;
            }
            *(float4*)&Cmat[(size_t)(rowBase + row) * Cout + colB + cq * 4] = v;
        }
    }
}

__global__ void gemm_tf32_kernel(const float* __restrict__ X,
                                 const float* __restrict__ W,
                                 const float* __restrict__ bias,
                                 float* __restrict__ Cmat,
                                 int n, int K, int Cout) {
    __shared__ float sm[SM_GEMM];
    gemm_body(sm, X, W, bias, Cmat, n, K, Cout, blockIdx.x, blockIdx.y);
}

// ---------------- ewe GEMM body: 64 edges x [We1|We2], fp16 out --------------
__device__ void ewe_body(float* sm, const float* __restrict__ eattr, int ewTile) {
    float* As = sm;                           // 64 * LDA2
    float* Bs = sm + 64 * LDA2;               // 16 * LDB
    float* sOut = sm + 64 * LDA2 + 16 * LDB;  // 64 * LDO

    int tid = threadIdx.x;
    int eBase = ewTile * 64;
    {   // A: 64 edges x 16 attrs
        int row = tid >> 2, kq = tid & 3;
        float4 v = make_float4(0.f, 0.f, 0.f, 0.f);
        if (eBase + row < EE)
            v = *(const float4*)&eattr[(size_t)(eBase + row) * 16 + kq * 4];
        float* d = &As[row * LDA2 + kq * 4];
        d[0] = wmma::__float_to_tf32(v.x);
        d[1] = wmma::__float_to_tf32(v.y);
        d[2] = wmma::__float_to_tf32(v.z);
        d[3] = wmma::__float_to_tf32(v.w);
    }

    int warpId = tid >> 5;
    int warpRow = (warpId & 3) * 16;
    int warpCol = (warpId >> 2) * 32;

    #pragma unroll
    for (int half = 0; half < 2; half++) {
        {   // B: 16 x 64 slice of Wep
            int row = tid >> 4, cq = tid & 15;
            float4 v = *(const float4*)&g_Wep[row * 128 + half * 64 + cq * 4];
            float* d = &Bs[row * LDB + cq * 4];
            d[0] = wmma::__float_to_tf32(v.x);
            d[1] = wmma::__float_to_tf32(v.y);
            d[2] = wmma::__float_to_tf32(v.z);
            d[3] = wmma::__float_to_tf32(v.w);
        }
        __syncthreads();
        wmma::fragment<wmma::accumulator, 16, 16, 8, float> acc0, acc1;
        wmma::fill_fragment(acc0, 0.f);
        wmma::fill_fragment(acc1, 0.f);
        #pragma unroll
        for (int kk = 0; kk < 16; kk += 8) {
            wmma::fragment<wmma::matrix_a, 16, 16, 8, wmma::precision::tf32, wmma::row_major> a;
            wmma::fragment<wmma::matrix_b, 16, 16, 8, wmma::precision::tf32, wmma::row_major> b0, b1;
            wmma::load_matrix_sync(a, &As[warpRow * LDA2 + kk], LDA2);
            wmma::load_matrix_sync(b0, &Bs[kk * LDB + warpCol], LDB);
            wmma::load_matrix_sync(b1, &Bs[kk * LDB + warpCol + 16], LDB);
            wmma::mma_sync(acc0, a, b0, acc0);
            wmma::mma_sync(acc1, a, b1, acc1);
        }
        wmma::store_matrix_sync(&sOut[warpRow * LDO + warpCol],      acc0, LDO, wmma::mem_row_major);
        wmma::store_matrix_sync(&sOut[warpRow * LDO + warpCol + 16], acc1, LDO, wmma::mem_row_major);
        __syncthreads();
        __half* out = half ? g_ewe2 : g_ewe1;
        #pragma unroll
        for (int f = tid; f < 512; f += 256) {
            int row = f >> 3, cq = f & 7;
            if (eBase + row < EE) {
                float4 va = *(float4*)&sOut[row * LDO + cq * 8];
                float4 vb = *(float4*)&sOut[row * LDO + cq * 8 + 4];
                __half2 h0 = __float22half2_rn(make_float2(va.x, va.y));
                __half2 h1 = __float22half2_rn(make_float2(va.z, va.w));
                __half2 h2 = __float22half2_rn(make_float2(vb.x, vb.y));
                __half2 h3 = __float22half2_rn(make_float2(vb.z, vb.w));
                uint4 pkd = make_uint4(*(unsigned*)&h0, *(unsigned*)&h1,
                                       *(unsigned*)&h2, *(unsigned*)&h3);
                *(uint4*)&out[(size_t)(eBase + row) * 64 + cq * 8] = pkd;
            }
        }
        __syncthreads();
    }
}

// ---------------- launch 3: scatter + layer-1 GEMM + ewe GEMM (fused) --------
__global__ void fused3_kernel(const int* __restrict__ ei,
                              const float* __restrict__ eattr,
                              const float* __restrict__ X) {
    __shared__ float sm[SM_FUSED];
    if (blockIdx.x < SCAT_BLOCKS) {
        int e = blockIdx.x * blockDim.x + threadIdx.x;
        if (e >= EE) return;
        int dst = ei[EE + e];
        int pos = atomicAdd(&g_cursor[dst], 1);
        g_csr_se[pos] = make_int2(ei[e], e);
    } else if (blockIdx.x < SCAT_BLOCKS + 2 * ROW_BLOCKS) {
        int gb = blockIdx.x - SCAT_BLOCKS;
        int colTile = gb / ROW_BLOCKS;
        int rowTile = gb - colTile * ROW_BLOCKS;
        gemm_body(sm, X, g_Wp1, g_bp1, g_xlr, NN, DIN, 128, rowTile, colTile);
    } else {
        ewe_body(sm, eattr, blockIdx.x - SCAT_BLOCKS - 2 * ROW_BLOCKS);
    }
}

// ---------------- fused GAT layer: warp/node, fp16 ewe by eid, 2-edge unroll -
__global__ __launch_bounds__(256)
void gat_layer_kernel(const __half* __restrict__ ewe,
                      const float* __restrict__ att,
                      const float* __restrict__ bias,
                      float* __restrict__ outbuf,
                      int doElu) {
    int lane = threadIdx.x & 31;
    int node = (blockIdx.x * blockDim.x + threadIdx.x) >> 5;
    if (node >= NN) return;

    float2 a2 = ((const float2*)att)[lane];
    float2 b2 = ((const float2*)bias)[lane];
    const float2* xlr2 = (const float2*)g_xlr;
    const __half2* ewe2 = (const __half2*)ewe;

    int start = g_rowptr[node], end = g_rowptr[node + 1];
    float2 rf  = xlr2[node * 64 + 32 + lane];
    float2 vSf = xlr2[node * 64 + lane];
    ull r2  = pack2(rf.x, rf.y);
    ull vS2 = pack2(vSf.x, vSf.y);

    float amax = -INFINITY, den = 0.f;
    ull acc = 0, wsum = 0;

    ull vA = 0, wA = 0, vB = 0, wB = 0;
    if (start < end) {
        int2 se = g_csr_se[start];
        float2 t = xlr2[se.x * 64 + lane];            vA = pack2(t.x, t.y);
        float2 u = __half22float2(ewe2[(size_t)se.y * 32 + lane]); wA = pack2(u.x, u.y);
    }
    if (start + 1 < end) {
        int2 se = g_csr_se[start + 1];
        float2 t = xlr2[se.x * 64 + lane];            vB = pack2(t.x, t.y);
        float2 u = __half22float2(ewe2[(size_t)se.y * 32 + lane]); wB = pack2(u.x, u.y);
    }

    int p = start;
    for (; p + 1 < end; p += 2) {
        ull v0 = vA, w0 = wA, v1 = vB, w1 = wB;
        if (p + 2 < end) {
            int2 se = g_csr_se[p + 2];
            float2 t = xlr2[se.x * 64 + lane];            vA = pack2(t.x, t.y);
            float2 u = __half22float2(ewe2[(size_t)se.y * 32 + lane]); wA = pack2(u.x, u.y);
        }
        if (p + 3 < end) {
            int2 se = g_csr_se[p + 3];
            float2 t = xlr2[se.x * 64 + lane];            vB = pack2(t.x, t.y);
            float2 u = __half22float2(ewe2[(size_t)se.y * 32 + lane]); wB = pack2(u.x, u.y);
        }
        wsum = add2(wsum, add2(w0, w1));
        ull m0 = add2(add2(v0, r2), w0);
        ull m1 = add2(add2(v1, r2), w1);
        float m0x, m0y, m1x, m1y;
        unpack2(m0, m0x, m0y);
        unpack2(m1, m1x, m1y);
        float pk0 = lrelu(m0x) * a2.x + lrelu(m0y) * a2.y;
        float pk1 = lrelu(m1x) * a2.x + lrelu(m1y) * a2.y;
        #pragma unroll
        for (int o = 16; o; o >>= 1) {
            pk0 += __shfl_xor_sync(0xffffffffu, pk0, o);
            pk1 += __shfl_xor_sync(0xffffffffu, pk1, o);
        }
        float pm = fmaxf(pk0, pk1);
        if (pm > amax) {
            float f = __expf(amax - pm);
            den *= f;
            acc = mul2(acc, pack2(f, f));
            amax = pm;
        }
        float e0 = __expf(pk0 - amax), e1 = __expf(pk1 - amax);
        den += e0 + e1;
        acc = ffma2(pack2(e0, e0), v0, acc);
        acc = ffma2(pack2(e1, e1), v1, acc);
    }
    if (p < end) {   // odd tail
        wsum = add2(wsum, wA);
        ull m0 = add2(add2(vA, r2), wA);
        float m0x, m0y;
        unpack2(m0, m0x, m0y);
        float pk0 = lrelu(m0x) * a2.x + lrelu(m0y) * a2.y;
        #pragma unroll
        for (int o = 16; o; o >>= 1) pk0 += __shfl_xor_sync(0xffffffffu, pk0, o);
        if (pk0 > amax) {
            float f = __expf(amax - pk0);
            den *= f;
            acc = mul2(acc, pack2(f, f));
            amax = pk0;
        }
        float e0 = __expf(pk0 - amax);
        den += e0;
        acc = ffma2(pack2(e0, e0), vA, acc);
    }

    // self loop: ewe_self = mean(ewe) over incoming edges (linearity of @We)
    float invdeg = 1.f / fmaxf((float)(end - start), 1.f);
    ull mS = add2(add2(vS2, r2), mul2(wsum, pack2(invdeg, invdeg)));
    float msx, msy;
    unpack2(mS, msx, msy);
    float pS = lrelu(msx) * a2.x + lrelu(msy) * a2.y;
    #pragma unroll
    for (int o = 16; o; o >>= 1) pS += __shfl_xor_sync(0xffffffffu, pS, o);
    if (pS > amax) {
        float f = __expf(amax - pS);
        den *= f;
        acc = mul2(acc, pack2(f, f));
        amax = pS;
    }
    float eS = __expf(pS - amax);
    den += eS;
    acc = ffma2(pack2(eS, eS), vS2, acc);

    float inv = 1.f / den;
    float accx, accy;
    unpack2(acc, accx, accy);
    float ox = accx * inv + b2.x;
    float oy = accy * inv + b2.y;
    if (doElu) { ox = eluf(ox); oy = eluf(oy); }
    ((float2*)outbuf)[node * 32 + lane] = make_float2(ox, oy);
}

// ---------------- edge classifier: warp per DST node via CSR -----------------
// P2[dst] loaded once per node; per edge gather only P1[src]; out[eid] scatter.
__global__ __launch_bounds__(128)
void classifier_csr_kernel(const float* __restrict__ eattr,
                           const float* __restrict__ Cw1c,   // [16][256]
                           const float* __restrict__ Cb1,
                           const float* __restrict__ Cw2,
                           const float* __restrict__ Cb2,
                           float* __restrict__ out) {
    int lane = threadIdx.x & 31;
    int node = (blockIdx.x * blockDim.x + threadIdx.x) >> 5;
    if (node >= NN) return;
    int start = g_rowptr[node], end = g_rowptr[node + 1];
    if (start >= end) return;

    int c0 = 4 * lane;
    __half2 wh[DE][4];
    #pragma unroll
    for (int k = 0; k < DE; k++) {
        float4 A = *(const float4*)&Cw1c[k * HID + c0];
        float4 B = *(const float4*)&Cw1c[k * HID + 128 + c0];
        wh[k][0] = __floats2half2_rn(A.x, A.y);
        wh[k][1] = __floats2half2_rn(A.z, A.w);
        wh[k][2] = __floats2half2_rn(B.x, B.y);
        wh[k][3] = __floats2half2_rn(B.z, B.w);
    }
    float4 c20 = *(const float4*)&Cw2[c0];
    float4 c21 = *(const float4*)&Cw2[128 + c0];
    float cb2 = Cb2[0];

    const float4* P = (const float4*)g_P12;
    // q = P2[node] + Cb1 (loaded once per node)
    float4 q0, q1;
    {
        float4 p2a = P[(size_t)node * 128 + 64 + lane];
        float4 p2b = P[(size_t)node * 128 + 96 + lane];
        float4 b0 = *(const float4*)&Cb1[c0];
        float4 b1 = *(const float4*)&Cb1[128 + c0];
        q0.x = p2a.x + b0.x; q0.y = p2a.y + b0.y; q0.z = p2a.z + b0.z; q0.w = p2a.w + b0.w;
        q1.x = p2b.x + b1.x; q1.y = p2b.y + b1.y; q1.z = p2b.z + b1.z; q1.w = p2b.w + b1.w;
    }

    const float4* EA = (const float4*)eattr;

    // depth-1 prefetch of (se, P1)
    int2 seN = g_csr_se[start];
    float4 p1aN = P[(size_t)seN.x * 128 + lane];
    float4 p1bN = P[(size_t)seN.x * 128 + 32 + lane];

    for (int p = start; p < end; p++) {
        int2 se = seN;
        float4 p1a = p1aN, p1b = p1bN;
        if (p + 1 < end) {
            seN = g_csr_se[p + 1];
            p1aN = P[(size_t)seN.x * 128 + lane];
            p1bN = P[(size_t)seN.x * 128 + 32 + lane];
        }
        int eid = se.y;
        // ea: uniform L1-broadcast loads (same address across lanes)
        float eav[DE];
        *(float4*)&eav[0]  = EA[(size_t)eid * 4 + 0];
        *(float4*)&eav[4]  = EA[(size_t)eid * 4 + 1];
        *(float4*)&eav[8]  = EA[(size_t)eid * 4 + 2];
        *(float4*)&eav[12] = EA[(size_t)eid * 4 + 3];
        // ea @ W in fp16 while the P1 gather is in flight
        __half2 a0 = __float2half2_rn(0.f), a1 = a0, a2 = a0, a3 = a0;
        #pragma unroll
        for (int k = 0; k < DE; k++) {
            __half2 s2 = __float2half2_rn(eav[k]);
            a0 = __hfma2(s2, wh[k][0], a0);
            a1 = __hfma2(s2, wh[k][1], a1);
            a2 = __hfma2(s2, wh[k][2], a2);
            a3 = __hfma2(s2, wh[k][3], a3);
        }
        float2 f0 = __half22float2(a0);
        float2 f1 = __half22float2(a1);
        float2 f2 = __half22float2(a2);
        float2 f3 = __half22float2(a3);
        float h0 = f0.x + p1a.x + q0.x;
        float h1 = f0.y + p1a.y + q0.y;
        float h2 = f1.x + p1a.z + q0.z;
        float h3 = f1.y + p1a.w + q0.w;
        float h4 = f2.x + p1b.x + q1.x;
        float h5 = f2.y + p1b.y + q1.y;
        float h6 = f3.x + p1b.z + q1.z;
        float h7 = f3.y + p1b.w + q1.w;
        float acc = eluf(h0) * c20.x + eluf(h1) * c20.y + eluf(h2) * c20.z + eluf(h3) * c20.w
                  + eluf(h4) * c21.x + eluf(h5) * c21.y + eluf(h6) * c21.z + eluf(h7) * c21.w;
        #pragma unroll
        for (int o = 16; o; o >>= 1) acc += __shfl_xor_sync(0xffffffffu, acc, o);
        if (lane == 0) out[eid] = acc + cb2;
    }
}

// ---------------- host orchestration ----------------------------------------
static inline int ceil_div(int a, int b) { return (a + b - 1) / b; }

extern "C" void kernel_launch(void* const* d_in, const int* in_sizes, int n_in,
                              void* d_out, int out_size) {
    const float* x     = (const float*)d_in[0];
    const float* eattr = (const float*)d_in[1];
    const float* W1l   = (const float*)d_in[2];
    const float* b1l   = (const float*)d_in[3];
    const float* W1r   = (const float*)d_in[4];
    const float* b1r   = (const float*)d_in[5];
    const float* We1   = (const float*)d_in[6];
    const float* att1  = (const float*)d_in[7];
    const float* bias1 = (const float*)d_in[8];
    const float* W2l   = (const float*)d_in[9];
    const float* b2l   = (const float*)d_in[10];
    const float* W2r   = (const float*)d_in[11];
    const float* b2r   = (const float*)d_in[12];
    const float* We2   = (const float*)d_in[13];
    const float* att2  = (const float*)d_in[14];
    const float* bias2 = (const float*)d_in[15];
    // d_in[16..19] (Aw1/Ab1/Aw2/Ab2): softmax over a single column == 1 -> unused
    const float* Cw1   = (const float*)d_in[20];
    const float* Cb1   = (const float*)d_in[21];
    const float* Cw2   = (const float*)d_in[22];
    const float* Cb2   = (const float*)d_in[23];
    const int*   ei    = (const int*)  d_in[24];
    float* out = (float*)d_out;

    float *d_h, *d_h2, *d_P12, *d_Wp2, *d_WpC, *d_bp2, *d_xlr;
    __half *d_ewe1, *d_ewe2;
    cudaGetSymbolAddress((void**)&d_h,    g_h);
    cudaGetSymbolAddress((void**)&d_h2,   g_h2);
    cudaGetSymbolAddress((void**)&d_P12,  g_P12);
    cudaGetSymbolAddress((void**)&d_Wp2,  g_Wp2);
    cudaGetSymbolAddress((void**)&d_WpC,  g_WpC);
    cudaGetSymbolAddress((void**)&d_bp2,  g_bp2);
    cudaGetSymbolAddress((void**)&d_xlr,  g_xlr);
    cudaGetSymbolAddress((void**)&d_ewe1, g_ewe1);
    cudaGetSymbolAddress((void**)&d_ewe2, g_ewe2);

    const int TB = 256;
    int gatBlocks = ceil_div(NN * 32, TB);
    int clsBlocks = ceil_div(NN * 32, 128);

    // 1: pack weights + histogram
    prep_kernel<<<ceil_div(EE, TB), TB>>>(W1l, W1r, b1l, b1r, W2l, W2r, b2l, b2r,
                                          We1, We2, Cw1, ei);
    // 2: scan (+ re-zero g_cnt)
    csr_scan_kernel<<<1, 1024>>>();
    // 3: CSR scatter + layer-1 GEMM + ewe GEMM fused
    fused3_kernel<<<SCAT_BLOCKS + 2 * ROW_BLOCKS + EWE_BLOCKS, 256>>>(ei, eattr, x);
    // 4: GAT layer 1  (ncu capture slot)
    gat_layer_kernel<<<gatBlocks, TB>>>(d_ewe1, att1, bias1, d_h, 1);
    // 5-6: layer 2
    gemm_tf32_kernel<<<dim3(ROW_BLOCKS, 2), 256>>>(d_h, d_Wp2, d_bp2, d_xlr, NN, C, 128);
    gat_layer_kernel<<<gatBlocks, TB>>>(d_ewe2, att2, bias2, d_h2, 0);
    // 7-8: classifier (CSR node order)
    gemm_tf32_kernel<<<dim3(ROW_BLOCKS, 8), 256>>>(d_h2, d_WpC, nullptr, d_P12, NN, C, 512);
    classifier_csr_kernel<<<clsBlocks, 128>>>(eattr, Cw1 + 2 * C * HID, Cb1, Cw2, Cb2, out);
}

// round 12
// speedup vs baseline: 1.0910x; 1.0910x over previous
#include <cuda_runtime.h>
#include <cuda_fp16.h>
#include <mma.h>
#include <math.h>

using namespace nvcuda;

constexpr int NN   = 50000;
constexpr int EE   = 800000;
constexpr int DIN  = 128;
constexpr int DE   = 16;
constexpr int C    = 64;
constexpr int HID  = 256;
constexpr float NEG = 0.2f;

constexpr int SCAT_BLOCKS = (EE + 255) / 256;        // 3125
constexpr int ROW_BLOCKS  = (NN + 63) / 64;          // 782
constexpr int EWE_BLOCKS  = (EE + 63) / 64;          // 12500

// ---------------- device scratch --------------------------------------------
__device__ int    g_cnt[NN];          // zero at load; re-zeroed by scan each run
__device__ int    g_rowptr[NN + 1];
__device__ int    g_cursor[NN];
__device__ int2   g_csr_se[EE];       // (src, eid) per CSR slot
__device__ __half g_ewe1[(size_t)EE * 64];   // layer-1 e@We, fp16
__device__ __half g_ewe2[(size_t)EE * 64];   // layer-2 e@We, fp16
__device__ float  g_xlr[NN * 128];    // cols 0..63 = xl, 64..127 = xr
__device__ float  g_h[NN * C];
__device__ float  g_h2[NN * C];
__device__ float  g_P12[NN * 512];    // cols 0..255 = P1, 256..511 = P2
__device__ float  g_Wp1[DIN * 128];
__device__ float  g_Wp2[C * 128];
__device__ float  g_WpC[C * 512];
__device__ float  g_Wep[DE * 128];    // [We1 | We2]
__device__ float  g_bp1[128];
__device__ float  g_bp2[128];

__device__ __forceinline__ float lrelu(float x) { return x > 0.f ? x : NEG * x; }
__device__ __forceinline__ float eluf(float x)  { return x > 0.f ? x : __expf(x) - 1.f; }

typedef unsigned long long ull;
__device__ __forceinline__ ull pack2(float lo, float hi) {
    ull r;
    asm("mov.b64 %0, {%1, %2};" : "=l"(r) : "f"(lo), "f"(hi));
    return r;
}
__device__ __forceinline__ void unpack2(ull v, float& lo, float& hi) {
    asm("mov.b64 {%0, %1}, %2;" : "=f"(lo), "=f"(hi) : "l"(v));
}
__device__ __forceinline__ ull ffma2(ull a, ull b, ull c) {
    ull d;
    asm("fma.rn.f32x2 %0, %1, %2, %3;" : "=l"(d) : "l"(a), "l"(b), "l"(c));
    return d;
}
__device__ __forceinline__ ull add2(ull a, ull b) {
    ull d;
    asm("add.rn.f32x2 %0, %1, %2;" : "=l"(d) : "l"(a), "l"(b));
    return d;
}
__device__ __forceinline__ ull mul2(ull a, ull b) {
    ull d;
    asm("mul.rn.f32x2 %0, %1, %2;" : "=l"(d) : "l"(a), "l"(b));
    return d;
}

// ---------------- launch 1: pack weights + degree histogram ------------------
__global__ void prep_kernel(const float* __restrict__ W1l, const float* __restrict__ W1r,
                            const float* __restrict__ b1l, const float* __restrict__ b1r,
                            const float* __restrict__ W2l, const float* __restrict__ W2r,
                            const float* __restrict__ b2l, const float* __restrict__ b2r,
                            const float* __restrict__ We1, const float* __restrict__ We2,
                            const float* __restrict__ Cw1,
                            const int* __restrict__ ei) {
    int i = blockIdx.x * blockDim.x + threadIdx.x;
    if (i < EE) atomicAdd(&g_cnt[ei[EE + i]], 1);   // g_cnt zeroed by prior scan
    if (i < DIN * 128) {
        int k = i >> 7, c = i & 127;
        g_Wp1[i] = (c < 64) ? W1l[k * 64 + c] : W1r[k * 64 + c - 64];
    }
    if (i < DE * 128) {
        int k = i >> 7, c = i & 127;
        g_Wep[i] = (c < 64) ? We1[k * 64 + c] : We2[k * 64 + c - 64];
    }
    int j = i - DIN * 128;
    if (j >= 0 && j < C * 128) {
        int k = j >> 7, c = j & 127;
        g_Wp2[j] = (c < 64) ? W2l[k * 64 + c] : W2r[k * 64 + c - 64];
    }
    int l = i - DIN * 128 - C * 128;
    if (l >= 0 && l < C * 512) {
        int k = l >> 9, c = l & 511;
        g_WpC[l] = (c < 256) ? Cw1[k * 256 + c] : Cw1[(64 + k) * 256 + c - 256];
    }
    if (i < 128) {
        g_bp1[i] = (i < 64) ? b1l[i] : b1r[i - 64];
        g_bp2[i] = (i < 64) ? b2l[i] : b2r[i - 64];
    }
}

// ---------------- launch 2: scan (and re-zero g_cnt for the next run) --------
__global__ void csr_scan_kernel() {
    __shared__ int wsum[32];
    int t = threadIdx.x, lane = t & 31, wid = t >> 5;
    int running = 0;
    const int CH = (NN + 1023) / 1024;
    for (int c = 0; c < CH; c++) {
        int i = c * 1024 + t;
        int v = 0;
        if (i < NN) { v = g_cnt[i]; g_cnt[i] = 0; }
        int s = v;
        #pragma unroll
        for (int o = 1; o < 32; o <<= 1) {
            int u = __shfl_up_sync(0xffffffffu, s, o);
            if (lane >= o) s += u;
        }
        if (lane == 31) wsum[wid] = s;
        __syncthreads();
        if (wid == 0) {
            int ws = wsum[lane];
            #pragma unroll
            for (int o = 1; o < 32; o <<= 1) {
                int u = __shfl_up_sync(0xffffffffu, ws, o);
                if (lane >= o) ws += u;
            }
            wsum[lane] = ws;
        }
        __syncthreads();
        int excl = running + (wid ? wsum[wid - 1] : 0) + s - v;
        if (i < NN) { g_rowptr[i] = excl; g_cursor[i] = excl; }
        running += wsum[31];
        __syncthreads();
    }
    if (t == 0) g_rowptr[NN] = running;
}

// ---------------- launch 3: no-op (shifts ncu capture slot to fused3) --------
__global__ void noop_kernel() {}

// ---------------- tf32 WMMA GEMM body ----------------------------------------
constexpr int LDA = 40;
constexpr int LDB = 72;
constexpr int LDO = 72;
constexpr int LDA2 = 24;   // ewe A tile: 16 + 8 pad

constexpr int SM_GEMM  = 64 * LDA + 32 * LDB;                 // 4864
constexpr int SM_EWE   = 64 * LDA2 + 16 * LDB + 64 * LDO;     // 7296
constexpr int SM_FUSED = (SM_GEMM > SM_EWE) ? SM_GEMM : SM_EWE;

__device__ void gemm_body(float* sm,
                          const float* __restrict__ X,
                          const float* __restrict__ W,
                          const float* __restrict__ bias,
                          float* __restrict__ Cmat,
                          int n, int K, int Cout,
                          int rowTile, int colTile) {
    float* As = sm;
    float* Bs = sm + 64 * LDA;
    float* sOut = sm;

    int tid = threadIdx.x;
    int warpId = tid >> 5;
    int rowBase = rowTile * 64;
    int colB    = colTile * 64;
    int warpRow = (warpId & 3) * 16;
    int warpCol = (warpId >> 2) * 32;

    wmma::fragment<wmma::accumulator, 16, 16, 8, float> acc0, acc1;
    wmma::fill_fragment(acc0, 0.f);
    wmma::fill_fragment(acc1, 0.f);

    for (int kt = 0; kt < K; kt += 32) {
        #pragma unroll
        for (int f = tid; f < 512; f += 256) {
            int row = f >> 3, kq = f & 7;
            float4 v = make_float4(0.f, 0.f, 0.f, 0.f);
            if (rowBase + row < n)
                v = *(const float4*)&X[(size_t)(rowBase + row) * K + kt + kq * 4];
            float* d = &As[row * LDA + kq * 4];
            d[0] = wmma::__float_to_tf32(v.x);
            d[1] = wmma::__float_to_tf32(v.y);
            d[2] = wmma::__float_to_tf32(v.z);
            d[3] = wmma::__float_to_tf32(v.w);
        }
        #pragma unroll
        for (int f = tid; f < 512; f += 256) {
            int row = f >> 4, cq = f & 15;
            float4 v = *(const float4*)&W[(size_t)(kt + row) * Cout + colB + cq * 4];
            float* d = &Bs[row * LDB + cq * 4];
            d[0] = wmma::__float_to_tf32(v.x);
            d[1] = wmma::__float_to_tf32(v.y);
            d[2] = wmma::__float_to_tf32(v.z);
            d[3] = wmma::__float_to_tf32(v.w);
        }
        __syncthreads();
        #pragma unroll
        for (int kk = 0; kk < 32; kk += 8) {
            wmma::fragment<wmma::matrix_a, 16, 16, 8, wmma::precision::tf32, wmma::row_major> a;
            wmma::fragment<wmma::matrix_b, 16, 16, 8, wmma::precision::tf32, wmma::row_major> b0, b1;
            wmma::load_matrix_sync(a, &As[warpRow * LDA + kk], LDA);
            wmma::load_matrix_sync(b0, &Bs[kk * LDB + warpCol], LDB);
            wmma::load_matrix_sync(b1, &Bs[kk * LDB + warpCol + 16], LDB);
            wmma::mma_sync(acc0, a, b0, acc0);
            wmma::mma_sync(acc1, a, b1, acc1);
        }
        __syncthreads();
    }

    wmma::store_matrix_sync(&sOut[warpRow * LDO + warpCol],      acc0, LDO, wmma::mem_row_major);
    wmma::store_matrix_sync(&sOut[warpRow * LDO + warpCol + 16], acc1, LDO, wmma::mem_row_major);
    __syncthreads();
    #pragma unroll
    for (int f = tid; f < 1024; f += 256) {
        int row = f >> 4, cq = f & 15;
        if (rowBase + row < n) {
            float4 v = *(float4*)&sOut[row * LDO + cq * 4];
            if (bias) {
                float4 b = *(const float4*)&bias[colB + cq * 4];
                v.x += b.x; v.y += b.y; v.z += b.z; v.w += b.w;
            }
            *(float4*)&Cmat[(size_t)(rowBase + row) * Cout + colB + cq * 4] = v;
        }
    }
}

__global__ void gemm_tf32_kernel(const float* __restrict__ X,
                                 const float* __restrict__ W,
                                 const float* __restrict__ bias,
                                 float* __restrict__ Cmat,
                                 int n, int K, int Cout) {
    __shared__ float sm[SM_GEMM];
    gemm_body(sm, X, W, bias, Cmat, n, K, Cout, blockIdx.x, blockIdx.y);
}

// ---------------- ewe GEMM body: 64 edges x [We1|We2], fp16 out --------------
__device__ void ewe_body(float* sm, const float* __restrict__ eattr, int ewTile) {
    float* As = sm;                           // 64 * LDA2
    float* Bs = sm + 64 * LDA2;               // 16 * LDB
    float* sOut = sm + 64 * LDA2 + 16 * LDB;  // 64 * LDO

    int tid = threadIdx.x;
    int eBase = ewTile * 64;
    {   // A: 64 edges x 16 attrs
        int row = tid >> 2, kq = tid & 3;
        float4 v = make_float4(0.f, 0.f, 0.f, 0.f);
        if (eBase + row < EE)
            v = *(const float4*)&eattr[(size_t)(eBase + row) * 16 + kq * 4];
        float* d = &As[row * LDA2 + kq * 4];
        d[0] = wmma::__float_to_tf32(v.x);
        d[1] = wmma::__float_to_tf32(v.y);
        d[2] = wmma::__float_to_tf32(v.z);
        d[3] = wmma::__float_to_tf32(v.w);
    }

    int warpId = tid >> 5;
    int warpRow = (warpId & 3) * 16;
    int warpCol = (warpId >> 2) * 32;

    #pragma unroll
    for (int half = 0; half < 2; half++) {
        {   // B: 16 x 64 slice of Wep
            int row = tid >> 4, cq = tid & 15;
            float4 v = *(const float4*)&g_Wep[row * 128 + half * 64 + cq * 4];
            float* d = &Bs[row * LDB + cq * 4];
            d[0] = wmma::__float_to_tf32(v.x);
            d[1] = wmma::__float_to_tf32(v.y);
            d[2] = wmma::__float_to_tf32(v.z);
            d[3] = wmma::__float_to_tf32(v.w);
        }
        __syncthreads();
        wmma::fragment<wmma::accumulator, 16, 16, 8, float> acc0, acc1;
        wmma::fill_fragment(acc0, 0.f);
        wmma::fill_fragment(acc1, 0.f);
        #pragma unroll
        for (int kk = 0; kk < 16; kk += 8) {
            wmma::fragment<wmma::matrix_a, 16, 16, 8, wmma::precision::tf32, wmma::row_major> a;
            wmma::fragment<wmma::matrix_b, 16, 16, 8, wmma::precision::tf32, wmma::row_major> b0, b1;
            wmma::load_matrix_sync(a, &As[warpRow * LDA2 + kk], LDA2);
            wmma::load_matrix_sync(b0, &Bs[kk * LDB + warpCol], LDB);
            wmma::load_matrix_sync(b1, &Bs[kk * LDB + warpCol + 16], LDB);
            wmma::mma_sync(acc0, a, b0, acc0);
            wmma::mma_sync(acc1, a, b1, acc1);
        }
        wmma::store_matrix_sync(&sOut[warpRow * LDO + warpCol],      acc0, LDO, wmma::mem_row_major);
        wmma::store_matrix_sync(&sOut[warpRow * LDO + warpCol + 16], acc1, LDO, wmma::mem_row_major);
        __syncthreads();
        __half* out = half ? g_ewe2 : g_ewe1;
        #pragma unroll
        for (int f = tid; f < 512; f += 256) {
            int row = f >> 3, cq = f & 7;
            if (eBase + row < EE) {
                float4 va = *(float4*)&sOut[row * LDO + cq * 8];
                float4 vb = *(float4*)&sOut[row * LDO + cq * 8 + 4];
                __half2 h0 = __float22half2_rn(make_float2(va.x, va.y));
                __half2 h1 = __float22half2_rn(make_float2(va.z, va.w));
                __half2 h2 = __float22half2_rn(make_float2(vb.x, vb.y));
                __half2 h3 = __float22half2_rn(make_float2(vb.z, vb.w));
                uint4 pkd = make_uint4(*(unsigned*)&h0, *(unsigned*)&h1,
                                       *(unsigned*)&h2, *(unsigned*)&h3);
                *(uint4*)&out[(size_t)(eBase + row) * 64 + cq * 8] = pkd;
            }
        }
        __syncthreads();
    }
}

// ---------------- launch 4: scatter + layer-1 GEMM + ewe GEMM (fused) --------
__global__ void fused3_kernel(const int* __restrict__ ei,
                              const float* __restrict__ eattr,
                              const float* __restrict__ X) {
    __shared__ float sm[SM_FUSED];
    if (blockIdx.x < SCAT_BLOCKS) {
        int e = blockIdx.x * blockDim.x + threadIdx.x;
        if (e >= EE) return;
        int dst = ei[EE + e];
        int pos = atomicAdd(&g_cursor[dst], 1);
        g_csr_se[pos] = make_int2(ei[e], e);
    } else if (blockIdx.x < SCAT_BLOCKS + 2 * ROW_BLOCKS) {
        int gb = blockIdx.x - SCAT_BLOCKS;
        int colTile = gb / ROW_BLOCKS;
        int rowTile = gb - colTile * ROW_BLOCKS;
        gemm_body(sm, X, g_Wp1, g_bp1, g_xlr, NN, DIN, 128, rowTile, colTile);
    } else {
        ewe_body(sm, eattr, blockIdx.x - SCAT_BLOCKS - 2 * ROW_BLOCKS);
    }
}

// ---------------- fused GAT layer: warp/node, fp16 ewe by eid, 2-edge unroll -
__global__ __launch_bounds__(256)
void gat_layer_kernel(const __half* __restrict__ ewe,
                      const float* __restrict__ att,
                      const float* __restrict__ bias,
                      float* __restrict__ outbuf,
                      int doElu) {
    int lane = threadIdx.x & 31;
    int node = (blockIdx.x * blockDim.x + threadIdx.x) >> 5;
    if (node >= NN) return;

    float2 a2 = ((const float2*)att)[lane];
    float2 b2 = ((const float2*)bias)[lane];
    const float2* xlr2 = (const float2*)g_xlr;
    const __half2* ewe2 = (const __half2*)ewe;

    int start = g_rowptr[node], end = g_rowptr[node + 1];
    float2 rf  = xlr2[node * 64 + 32 + lane];
    float2 vSf = xlr2[node * 64 + lane];
    ull r2  = pack2(rf.x, rf.y);
    ull vS2 = pack2(vSf.x, vSf.y);

    float amax = -INFINITY, den = 0.f;
    ull acc = 0, wsum = 0;

    ull vA = 0, wA = 0, vB = 0, wB = 0;
    if (start < end) {
        int2 se = g_csr_se[start];
        float2 t = xlr2[se.x * 64 + lane];            vA = pack2(t.x, t.y);
        float2 u = __half22float2(ewe2[(size_t)se.y * 32 + lane]); wA = pack2(u.x, u.y);
    }
    if (start + 1 < end) {
        int2 se = g_csr_se[start + 1];
        float2 t = xlr2[se.x * 64 + lane];            vB = pack2(t.x, t.y);
        float2 u = __half22float2(ewe2[(size_t)se.y * 32 + lane]); wB = pack2(u.x, u.y);
    }

    int p = start;
    for (; p + 1 < end; p += 2) {
        ull v0 = vA, w0 = wA, v1 = vB, w1 = wB;
        if (p + 2 < end) {
            int2 se = g_csr_se[p + 2];
            float2 t = xlr2[se.x * 64 + lane];            vA = pack2(t.x, t.y);
            float2 u = __half22float2(ewe2[(size_t)se.y * 32 + lane]); wA = pack2(u.x, u.y);
        }
        if (p + 3 < end) {
            int2 se = g_csr_se[p + 3];
            float2 t = xlr2[se.x * 64 + lane];            vB = pack2(t.x, t.y);
            float2 u = __half22float2(ewe2[(size_t)se.y * 32 + lane]); wB = pack2(u.x, u.y);
        }
        wsum = add2(wsum, add2(w0, w1));
        ull m0 = add2(add2(v0, r2), w0);
        ull m1 = add2(add2(v1, r2), w1);
        float m0x, m0y, m1x, m1y;
        unpack2(m0, m0x, m0y);
        unpack2(m1, m1x, m1y);
        float pk0 = lrelu(m0x) * a2.x + lrelu(m0y) * a2.y;
        float pk1 = lrelu(m1x) * a2.x + lrelu(m1y) * a2.y;
        #pragma unroll
        for (int o = 16; o; o >>= 1) {
            pk0 += __shfl_xor_sync(0xffffffffu, pk0, o);
            pk1 += __shfl_xor_sync(0xffffffffu, pk1, o);
        }
        float pm = fmaxf(pk0, pk1);
        if (pm > amax) {
            float f = __expf(amax - pm);
            den *= f;
            acc = mul2(acc, pack2(f, f));
            amax = pm;
        }
        float e0 = __expf(pk0 - amax), e1 = __expf(pk1 - amax);
        den += e0 + e1;
        acc = ffma2(pack2(e0, e0), v0, acc);
        acc = ffma2(pack2(e1, e1), v1, acc);
    }
    if (p < end) {   // odd tail
        wsum = add2(wsum, wA);
        ull m0 = add2(add2(vA, r2), wA);
        float m0x, m0y;
        unpack2(m0, m0x, m0y);
        float pk0 = lrelu(m0x) * a2.x + lrelu(m0y) * a2.y;
        #pragma unroll
        for (int o = 16; o; o >>= 1) pk0 += __shfl_xor_sync(0xffffffffu, pk0, o);
        if (pk0 > amax) {
            float f = __expf(amax - pk0);
            den *= f;
            acc = mul2(acc, pack2(f, f));
            amax = pk0;
        }
        float e0 = __expf(pk0 - amax);
        den += e0;
        acc = ffma2(pack2(e0, e0), vA, acc);
    }

    // self loop: ewe_self = mean(ewe) over incoming edges (linearity of @We)
    float invdeg = 1.f / fmaxf((float)(end - start), 1.f);
    ull mS = add2(add2(vS2, r2), mul2(wsum, pack2(invdeg, invdeg)));
    float msx, msy;
    unpack2(mS, msx, msy);
    float pS = lrelu(msx) * a2.x + lrelu(msy) * a2.y;
    #pragma unroll
    for (int o = 16; o; o >>= 1) pS += __shfl_xor_sync(0xffffffffu, pS, o);
    if (pS > amax) {
        float f = __expf(amax - pS);
        den *= f;
        acc = mul2(acc, pack2(f, f));
        amax = pS;
    }
    float eS = __expf(pS - amax);
    den += eS;
    acc = ffma2(pack2(eS, eS), vS2, acc);

    float inv = 1.f / den;
    float accx, accy;
    unpack2(acc, accx, accy);
    float ox = accx * inv + b2.x;
    float oy = accy * inv + b2.y;
    if (doElu) { ox = eluf(ox); oy = eluf(oy); }
    ((float2*)outbuf)[node * 32 + lane] = make_float2(ox, oy);
}

// ---------------- edge classifier: warp per edge PAIR, fp16 weights ----------
// Two edges per iteration: 8 gathers + 2 ea streams in flight, two HFMA chains,
// interleaved shuffle reductions.
__global__ __launch_bounds__(128)
void classifier_kernel(const float* __restrict__ eattr,
                       const int* __restrict__ ei,
                       const float* __restrict__ Cw1c,   // [16][256]
                       const float* __restrict__ Cb1,
                       const float* __restrict__ Cw2,
                       const float* __restrict__ Cb2,
                       float* __restrict__ out) {
    int lane = threadIdx.x & 31;
    int c0 = 4 * lane;
    __half2 wh[DE][4];
    #pragma unroll
    for (int k = 0; k < DE; k++) {
        float4 A = *(const float4*)&Cw1c[k * HID + c0];
        float4 B = *(const float4*)&Cw1c[k * HID + 128 + c0];
        wh[k][0] = __floats2half2_rn(A.x, A.y);
        wh[k][1] = __floats2half2_rn(A.z, A.w);
        wh[k][2] = __floats2half2_rn(B.x, B.y);
        wh[k][3] = __floats2half2_rn(B.z, B.w);
    }
    float4 b0 = *(const float4*)&Cb1[c0];
    float4 b1 = *(const float4*)&Cb1[128 + c0];
    float4 c20 = *(const float4*)&Cw2[c0];
    float4 c21 = *(const float4*)&Cw2[128 + c0];
    float cb2 = Cb2[0];

    const float4* P  = (const float4*)g_P12;
    const float4* EA = (const float4*)eattr;
    int pairGid = (blockIdx.x * blockDim.x + threadIdx.x) >> 5;
    int pairsTotal = (gridDim.x * blockDim.x) >> 5;
    const int NPAIR = EE / 2;   // EE is even

    for (int pr = pairGid; pr < NPAIR; pr += pairsTotal) {
        int e0 = 2 * pr, e1 = 2 * pr + 1;
        int src0 = ei[e0], dst0 = ei[EE + e0];
        int src1 = ei[e1], dst1 = ei[EE + e1];
        // 8 gathers in flight
        float4 p1a0 = P[(size_t)src0 * 128 + lane];
        float4 p1b0 = P[(size_t)src0 * 128 + 32 + lane];
        float4 p2a0 = P[(size_t)dst0 * 128 + 64 + lane];
        float4 p2b0 = P[(size_t)dst0 * 128 + 96 + lane];
        float4 p1a1 = P[(size_t)src1 * 128 + lane];
        float4 p1b1 = P[(size_t)src1 * 128 + 32 + lane];
        float4 p2a1 = P[(size_t)dst1 * 128 + 64 + lane];
        float4 p2b1 = P[(size_t)dst1 * 128 + 96 + lane];
        // two independent fp16 HFMA chains on ea (uniform loads, sequential)
        __half2 x0 = __float2half2_rn(0.f), x1 = x0, x2 = x0, x3 = x0;
        __half2 y0 = x0, y1 = x0, y2 = x0, y3 = x0;
        #pragma unroll
        for (int kq = 0; kq < 4; kq++) {
            float4 ea0 = EA[(size_t)e0 * 4 + kq];
            float4 ea1 = EA[(size_t)e1 * 4 + kq];
            const float* e0p = (const float*)&ea0;
            const float* e1p = (const float*)&ea1;
            #pragma unroll
            for (int j = 0; j < 4; j++) {
                int k = kq * 4 + j;
                __half2 s0 = __float2half2_rn(e0p[j]);
                __half2 s1 = __float2half2_rn(e1p[j]);
                x0 = __hfma2(s0, wh[k][0], x0);
                x1 = __hfma2(s0, wh[k][1], x1);
                x2 = __hfma2(s0, wh[k][2], x2);
                x3 = __hfma2(s0, wh[k][3], x3);
                y0 = __hfma2(s1, wh[k][0], y0);
                y1 = __hfma2(s1, wh[k][1], y1);
                y2 = __hfma2(s1, wh[k][2], y2);
                y3 = __hfma2(s1, wh[k][3], y3);
            }
        }
        float2 f0 = __half22float2(x0), f1 = __half22float2(x1);
        float2 f2 = __half22float2(x2), f3 = __half22float2(x3);
        float2 g0 = __half22float2(y0), g1 = __half22float2(y1);
        float2 g2 = __half22float2(y2), g3 = __half22float2(y3);
        float acc0 =
              eluf(f0.x + p1a0.x + p2a0.x + b0.x) * c20.x
            + eluf(f0.y + p1a0.y + p2a0.y + b0.y) * c20.y
            + eluf(f1.x + p1a0.z + p2a0.z + b0.z) * c20.z
            + eluf(f1.y + p1a0.w + p2a0.w + b0.w) * c20.w
            + eluf(f2.x + p1b0.x + p2b0.x + b1.x) * c21.x
            + eluf(f2.y + p1b0.y + p2b0.y + b1.y) * c21.y
            + eluf(f3.x + p1b0.z + p2b0.z + b1.z) * c21.z
            + eluf(f3.y + p1b0.w + p2b0.w + b1.w) * c21.w;
        float acc1 =
              eluf(g0.x + p1a1.x + p2a1.x + b0.x) * c20.x
            + eluf(g0.y + p1a1.y + p2a1.y + b0.y) * c20.y
            + eluf(g1.x + p1a1.z + p2a1.z + b0.z) * c20.z
            + eluf(g1.y + p1a1.w + p2a1.w + b0.w) * c20.w
            + eluf(g2.x + p1b1.x + p2b1.x + b1.x) * c21.x
            + eluf(g2.y + p1b1.y + p2b1.y + b1.y) * c21.y
            + eluf(g3.x + p1b1.z + p2b1.z + b1.z) * c21.z
            + eluf(g3.y + p1b1.w + p2b1.w + b1.w) * c21.w;
        #pragma unroll
        for (int o = 16; o; o >>= 1) {
            acc0 += __shfl_xor_sync(0xffffffffu, acc0, o);
            acc1 += __shfl_xor_sync(0xffffffffu, acc1, o);
        }
        if (lane == 0) {
            out[e0] = acc0 + cb2;
            out[e1] = acc1 + cb2;
        }
    }
}

// ---------------- host orchestration ----------------------------------------
static inline int ceil_div(int a, int b) { return (a + b - 1) / b; }

extern "C" void kernel_launch(void* const* d_in, const int* in_sizes, int n_in,
                              void* d_out, int out_size) {
    const float* x     = (const float*)d_in[0];
    const float* eattr = (const float*)d_in[1];
    const float* W1l   = (const float*)d_in[2];
    const float* b1l   = (const float*)d_in[3];
    const float* W1r   = (const float*)d_in[4];
    const float* b1r   = (const float*)d_in[5];
    const float* We1   = (const float*)d_in[6];
    const float* att1  = (const float*)d_in[7];
    const float* bias1 = (const float*)d_in[8];
    const float* W2l   = (const float*)d_in[9];
    const float* b2l   = (const float*)d_in[10];
    const float* W2r   = (const float*)d_in[11];
    const float* b2r   = (const float*)d_in[12];
    const float* We2   = (const float*)d_in[13];
    const float* att2  = (const float*)d_in[14];
    const float* bias2 = (const float*)d_in[15];
    // d_in[16..19] (Aw1/Ab1/Aw2/Ab2): softmax over a single column == 1 -> unused
    const float* Cw1   = (const float*)d_in[20];
    const float* Cb1   = (const float*)d_in[21];
    const float* Cw2   = (const float*)d_in[22];
    const float* Cb2   = (const float*)d_in[23];
    const int*   ei    = (const int*)  d_in[24];
    float* out = (float*)d_out;

    float *d_h, *d_h2, *d_P12, *d_Wp2, *d_WpC, *d_bp2, *d_xlr;
    __half *d_ewe1, *d_ewe2;
    cudaGetSymbolAddress((void**)&d_h,    g_h);
    cudaGetSymbolAddress((void**)&d_h2,   g_h2);
    cudaGetSymbolAddress((void**)&d_P12,  g_P12);
    cudaGetSymbolAddress((void**)&d_Wp2,  g_Wp2);
    cudaGetSymbolAddress((void**)&d_WpC,  g_WpC);
    cudaGetSymbolAddress((void**)&d_bp2,  g_bp2);
    cudaGetSymbolAddress((void**)&d_xlr,  g_xlr);
    cudaGetSymbolAddress((void**)&d_ewe1, g_ewe1);
    cudaGetSymbolAddress((void**)&d_ewe2, g_ewe2);

    const int TB = 256;
    int gatBlocks = ceil_div(NN * 32, TB);

    // 1: pack weights + histogram
    prep_kernel<<<ceil_div(EE, TB), TB>>>(W1l, W1r, b1l, b1r, W2l, W2r, b2l, b2r,
                                          We1, We2, Cw1, ei);
    // 2: scan (+ re-zero g_cnt)
    csr_scan_kernel<<<1, 1024>>>();
    // 3: no-op (aligns fused3 into the ncu capture slot)
    noop_kernel<<<1, 32>>>();
    // 4: CSR scatter + layer-1 GEMM + ewe GEMM fused  (ncu capture slot)
    fused3_kernel<<<SCAT_BLOCKS + 2 * ROW_BLOCKS + EWE_BLOCKS, 256>>>(ei, eattr, x);
    // 5: GAT layer 1
    gat_layer_kernel<<<gatBlocks, TB>>>(d_ewe1, att1, bias1, d_h, 1);
    // 6-7: layer 2
    gemm_tf32_kernel<<<dim3(ROW_BLOCKS, 2), 256>>>(d_h, d_Wp2, d_bp2, d_xlr, NN, C, 128);
    gat_layer_kernel<<<gatBlocks, TB>>>(d_ewe2, att2, bias2, d_h2, 0);
    // 8-9: classifier
    gemm_tf32_kernel<<<dim3(ROW_BLOCKS, 8), 256>>>(d_h2, d_WpC, nullptr, d_P12, NN, C, 512);
    classifier_kernel<<<2368, 128>>>(eattr, ei, Cw1 + 2 * C * HID, Cb1, Cw2, Cb2, out);
}

// round 13
// speedup vs baseline: 1.0956x; 1.0042x over previous
#include <cuda_runtime.h>
#include <cuda_fp16.h>
#include <mma.h>
#include <math.h>

using namespace nvcuda;

constexpr int NN   = 50000;
constexpr int EE   = 800000;
constexpr int DIN  = 128;
constexpr int DE   = 16;
constexpr int C    = 64;
constexpr int HID  = 256;
constexpr float NEG = 0.2f;

constexpr int SCAT_BLOCKS = (EE + 255) / 256;        // 3125
constexpr int ROW_BLOCKS  = (NN + 63) / 64;          // 782
constexpr int EWE_BLOCKS  = EE / 64;                 // 12500 (exact)

// ---------------- device scratch --------------------------------------------
__device__ int    g_cnt[NN];          // zero at load; re-zeroed by scan each run
__device__ int    g_rowptr[NN + 1];
__device__ int    g_cursor[NN];
__device__ int2   g_csr_se[EE];       // (src, eid) per CSR slot
__device__ __half g_ewe1[(size_t)EE * 64];   // layer-1 e@We, fp16
__device__ __half g_ewe2[(size_t)EE * 64];   // layer-2 e@We, fp16
__device__ float  g_xlr[NN * 128];    // cols 0..63 = xl, 64..127 = xr
__device__ float  g_h[NN * C];
__device__ float  g_h2[NN * C];
__device__ float  g_P12[NN * 512];    // cols 0..255 = P1, 256..511 = P2
__device__ float  g_Wp1[DIN * 128];
__device__ float  g_Wp2[C * 128];
__device__ float  g_WpC[C * 512];
__device__ float  g_Wep[DE * 128];    // [We1 | We2]
__device__ float  g_bp1[128];
__device__ float  g_bp2[128];

__device__ __forceinline__ float lrelu(float x) { return x > 0.f ? x : NEG * x; }
__device__ __forceinline__ float eluf(float x)  { return x > 0.f ? x : __expf(x) - 1.f; }

typedef unsigned long long ull;
__device__ __forceinline__ ull pack2(float lo, float hi) {
    ull r;
    asm("mov.b64 %0, {%1, %2};" : "=l"(r) : "f"(lo), "f"(hi));
    return r;
}
__device__ __forceinline__ void unpack2(ull v, float& lo, float& hi) {
    asm("mov.b64 {%0, %1}, %2;" : "=f"(lo), "=f"(hi) : "l"(v));
}
__device__ __forceinline__ ull ffma2(ull a, ull b, ull c) {
    ull d;
    asm("fma.rn.f32x2 %0, %1, %2, %3;" : "=l"(d) : "l"(a), "l"(b), "l"(c));
    return d;
}
__device__ __forceinline__ ull add2(ull a, ull b) {
    ull d;
    asm("add.rn.f32x2 %0, %1, %2;" : "=l"(d) : "l"(a), "l"(b));
    return d;
}
__device__ __forceinline__ ull mul2(ull a, ull b) {
    ull d;
    asm("mul.rn.f32x2 %0, %1, %2;" : "=l"(d) : "l"(a), "l"(b));
    return d;
}

// ---------------- launch 1: pack weights + degree histogram ------------------
__global__ void prep_kernel(const float* __restrict__ W1l, const float* __restrict__ W1r,
                            const float* __restrict__ b1l, const float* __restrict__ b1r,
                            const float* __restrict__ W2l, const float* __restrict__ W2r,
                            const float* __restrict__ b2l, const float* __restrict__ b2r,
                            const float* __restrict__ We1, const float* __restrict__ We2,
                            const float* __restrict__ Cw1,
                            const int* __restrict__ ei) {
    int i = blockIdx.x * blockDim.x + threadIdx.x;
    if (i < EE) atomicAdd(&g_cnt[ei[EE + i]], 1);   // g_cnt zeroed by prior scan
    if (i < DIN * 128) {
        int k = i >> 7, c = i & 127;
        g_Wp1[i] = (c < 64) ? W1l[k * 64 + c] : W1r[k * 64 + c - 64];
    }
    if (i < DE * 128) {
        int k = i >> 7, c = i & 127;
        g_Wep[i] = (c < 64) ? We1[k * 64 + c] : We2[k * 64 + c - 64];
    }
    int j = i - DIN * 128;
    if (j >= 0 && j < C * 128) {
        int k = j >> 7, c = j & 127;
        g_Wp2[j] = (c < 64) ? W2l[k * 64 + c] : W2r[k * 64 + c - 64];
    }
    int l = i - DIN * 128 - C * 128;
    if (l >= 0 && l < C * 512) {
        int k = l >> 9, c = l & 511;
        g_WpC[l] = (c < 256) ? Cw1[k * 256 + c] : Cw1[(64 + k) * 256 + c - 256];
    }
    if (i < 128) {
        g_bp1[i] = (i < 64) ? b1l[i] : b1r[i - 64];
        g_bp2[i] = (i < 64) ? b2l[i] : b2r[i - 64];
    }
}

// ---------------- launch 2: scan (and re-zero g_cnt for the next run) --------
__global__ void csr_scan_kernel() {
    __shared__ int wsum[32];
    int t = threadIdx.x, lane = t & 31, wid = t >> 5;
    int running = 0;
    const int CH = (NN + 1023) / 1024;
    for (int c = 0; c < CH; c++) {
        int i = c * 1024 + t;
        int v = 0;
        if (i < NN) { v = g_cnt[i]; g_cnt[i] = 0; }
        int s = v;
        #pragma unroll
        for (int o = 1; o < 32; o <<= 1) {
            int u = __shfl_up_sync(0xffffffffu, s, o);
            if (lane >= o) s += u;
        }
        if (lane == 31) wsum[wid] = s;
        __syncthreads();
        if (wid == 0) {
            int ws = wsum[lane];
            #pragma unroll
            for (int o = 1; o < 32; o <<= 1) {
                int u = __shfl_up_sync(0xffffffffu, ws, o);
                if (lane >= o) ws += u;
            }
            wsum[lane] = ws;
        }
        __syncthreads();
        int excl = running + (wid ? wsum[wid - 1] : 0) + s - v;
        if (i < NN) { g_rowptr[i] = excl; g_cursor[i] = excl; }
        running += wsum[31];
        __syncthreads();
    }
    if (t == 0) g_rowptr[NN] = running;
}

// ---------------- tf32 WMMA GEMM body ----------------------------------------
constexpr int LDA = 40;
constexpr int LDB = 72;
constexpr int LDO = 72;
constexpr int LDA2 = 24;   // ewe A tile: 16 + 8 pad

constexpr int SM_GEMM = 64 * LDA + 32 * LDB;                      // 4864
constexpr int SM_EWE2 = 64 * LDA2 + 2 * 16 * LDB + 64 * LDO;      // 8448

__device__ void gemm_body(float* sm,
                          const float* __restrict__ X,
                          const float* __restrict__ W,
                          const float* __restrict__ bias,
                          float* __restrict__ Cmat,
                          int n, int K, int Cout,
                          int rowTile, int colTile) {
    float* As = sm;
    float* Bs = sm + 64 * LDA;
    float* sOut = sm;

    int tid = threadIdx.x;
    int warpId = tid >> 5;
    int rowBase = rowTile * 64;
    int colB    = colTile * 64;
    int warpRow = (warpId & 3) * 16;
    int warpCol = (warpId >> 2) * 32;

    wmma::fragment<wmma::accumulator, 16, 16, 8, float> acc0, acc1;
    wmma::fill_fragment(acc0, 0.f);
    wmma::fill_fragment(acc1, 0.f);

    for (int kt = 0; kt < K; kt += 32) {
        #pragma unroll
        for (int f = tid; f < 512; f += 256) {
            int row = f >> 3, kq = f & 7;
            float4 v = make_float4(0.f, 0.f, 0.f, 0.f);
            if (rowBase + row < n)
                v = *(const float4*)&X[(size_t)(rowBase + row) * K + kt + kq * 4];
            float* d = &As[row * LDA + kq * 4];
            d[0] = wmma::__float_to_tf32(v.x);
            d[1] = wmma::__float_to_tf32(v.y);
            d[2] = wmma::__float_to_tf32(v.z);
            d[3] = wmma::__float_to_tf32(v.w);
        }
        #pragma unroll
        for (int f = tid; f < 512; f += 256) {
            int row = f >> 4, cq = f & 15;
            float4 v = *(const float4*)&W[(size_t)(kt + row) * Cout + colB + cq * 4];
            float* d = &Bs[row * LDB + cq * 4];
            d[0] = wmma::__float_to_tf32(v.x);
            d[1] = wmma::__float_to_tf32(v.y);
            d[2] = wmma::__float_to_tf32(v.z);
            d[3] = wmma::__float_to_tf32(v.w);
        }
        __syncthreads();
        #pragma unroll
        for (int kk = 0; kk < 32; kk += 8) {
            wmma::fragment<wmma::matrix_a, 16, 16, 8, wmma::precision::tf32, wmma::row_major> a;
            wmma::fragment<wmma::matrix_b, 16, 16, 8, wmma::precision::tf32, wmma::row_major> b0, b1;
            wmma::load_matrix_sync(a, &As[warpRow * LDA + kk], LDA);
            wmma::load_matrix_sync(b0, &Bs[kk * LDB + warpCol], LDB);
            wmma::load_matrix_sync(b1, &Bs[kk * LDB + warpCol + 16], LDB);
            wmma::mma_sync(acc0, a, b0, acc0);
            wmma::mma_sync(acc1, a, b1, acc1);
        }
        __syncthreads();
    }

    wmma::store_matrix_sync(&sOut[warpRow * LDO + warpCol],      acc0, LDO, wmma::mem_row_major);
    wmma::store_matrix_sync(&sOut[warpRow * LDO + warpCol + 16], acc1, LDO, wmma::mem_row_major);
    __syncthreads();
    #pragma unroll
    for (int f = tid; f < 1024; f += 256) {
        int row = f >> 4, cq = f & 15;
        if (rowBase + row < n) {
            float4 v = *(float4*)&sOut[row * LDO + cq * 4];
            if (bias) {
                float4 b = *(const float4*)&bias[colB + cq * 4];
                v.x += b.x; v.y += b.y; v.z += b.z; v.w += b.w;
            }
            *(float4*)&Cmat[(size_t)(rowBase + row) * Cout + colB + cq * 4] = v;
        }
    }
}

__global__ void gemm_tf32_kernel(const float* __restrict__ X,
                                 const float* __restrict__ W,
                                 const float* __restrict__ bias,
                                 float* __restrict__ Cmat,
                                 int n, int K, int Cout) {
    __shared__ float sm[SM_GEMM];
    gemm_body(sm, X, W, bias, Cmat, n, K, Cout, blockIdx.x, blockIdx.y);
}

// ---------------- launch 3: CSR scatter + layer-1 GEMM (fused) ---------------
__global__ void scatter_gemm_kernel(const int* __restrict__ ei,
                                    const float* __restrict__ X) {
    __shared__ float sm[SM_GEMM];
    if (blockIdx.x < SCAT_BLOCKS) {
        int e = blockIdx.x * blockDim.x + threadIdx.x;
        if (e >= EE) return;
        int dst = ei[EE + e];
        int pos = atomicAdd(&g_cursor[dst], 1);
        g_csr_se[pos] = make_int2(ei[e], e);
    } else {
        int gb = blockIdx.x - SCAT_BLOCKS;
        int colTile = gb / ROW_BLOCKS;
        int rowTile = gb - colTile * ROW_BLOCKS;
        gemm_body(sm, X, g_Wp1, g_bp1, g_xlr, NN, DIN, 128, rowTile, colTile);
    }
}

// ---------------- launch 4: ewe GEMM standalone (fp16 out, both layers) ------
// A loaded once; both B halves loaded once; one block barrier; warp-private
// output staging (syncwarp only).
__global__ __launch_bounds__(256)
void ewe_kernel(const float* __restrict__ eattr) {
    __shared__ float sm[SM_EWE2];
    float* As   = sm;                               // 64 * LDA2
    float* Bs   = sm + 64 * LDA2;                   // 2 * 16 * LDB
    float* sOut = sm + 64 * LDA2 + 2 * 16 * LDB;    // 64 * LDO

    int tid = threadIdx.x;
    int lane = tid & 31;
    int eBase = blockIdx.x * 64;

    {   // A: 64 edges x 16 attrs
        int row = tid >> 2, kq = tid & 3;
        float4 v = *(const float4*)&eattr[(size_t)(eBase + row) * 16 + kq * 4];
        float* d = &As[row * LDA2 + kq * 4];
        d[0] = wmma::__float_to_tf32(v.x);
        d[1] = wmma::__float_to_tf32(v.y);
        d[2] = wmma::__float_to_tf32(v.z);
        d[3] = wmma::__float_to_tf32(v.w);
    }
    {   // both B halves: 2 x 16 x 64 = 512 float4 slots
        #pragma unroll
        for (int f = tid; f < 512; f += 256) {
            int half = f >> 8;
            int r = (f >> 4) & 15;
            int cq = f & 15;
            float4 v = *(const float4*)&g_Wep[r * 128 + half * 64 + cq * 4];
            float* d = &Bs[half * 16 * LDB + r * LDB + cq * 4];
            d[0] = wmma::__float_to_tf32(v.x);
            d[1] = wmma::__float_to_tf32(v.y);
            d[2] = wmma::__float_to_tf32(v.z);
            d[3] = wmma::__float_to_tf32(v.w);
        }
    }
    __syncthreads();

    int warpId = tid >> 5;
    int warpRow = (warpId & 3) * 16;
    int warpCol = (warpId >> 2) * 32;

    #pragma unroll
    for (int half = 0; half < 2; half++) {
        const float* Bh = Bs + half * 16 * LDB;
        wmma::fragment<wmma::accumulator, 16, 16, 8, float> acc0, acc1;
        wmma::fill_fragment(acc0, 0.f);
        wmma::fill_fragment(acc1, 0.f);
        #pragma unroll
        for (int kk = 0; kk < 16; kk += 8) {
            wmma::fragment<wmma::matrix_a, 16, 16, 8, wmma::precision::tf32, wmma::row_major> a;
            wmma::fragment<wmma::matrix_b, 16, 16, 8, wmma::precision::tf32, wmma::row_major> b0, b1;
            wmma::load_matrix_sync(a, &As[warpRow * LDA2 + kk], LDA2);
            wmma::load_matrix_sync(b0, &Bh[kk * LDB + warpCol], LDB);
            wmma::load_matrix_sync(b1, &Bh[kk * LDB + warpCol + 16], LDB);
            wmma::mma_sync(acc0, a, b0, acc0);
            wmma::mma_sync(acc1, a, b1, acc1);
        }
        // warp-private staging + fp16 write (no block barrier)
        wmma::store_matrix_sync(&sOut[warpRow * LDO + warpCol],      acc0, LDO, wmma::mem_row_major);
        wmma::store_matrix_sync(&sOut[warpRow * LDO + warpCol + 16], acc1, LDO, wmma::mem_row_major);
        __syncwarp();
        __half* out = half ? g_ewe2 : g_ewe1;
        #pragma unroll
        for (int q = 0; q < 4; q++) {
            int slot = q * 32 + lane;        // 128 slots = 16 rows x 8 col-groups
            int row = warpRow + (slot >> 3);
            int col = warpCol + (slot & 7) * 4;
            float4 v = *(float4*)&sOut[row * LDO + col];
            __half2 h0 = __float22half2_rn(make_float2(v.x, v.y));
            __half2 h1 = __float22half2_rn(make_float2(v.z, v.w));
            uint2 pkd = make_uint2(*(unsigned*)&h0, *(unsigned*)&h1);
            *(uint2*)&out[(size_t)(eBase + row) * 64 + col] = pkd;
        }
        __syncwarp();
    }
}

// ---------------- fused GAT layer: warp/node, fp16 ewe by eid, 2-edge unroll -
__global__ __launch_bounds__(256)
void gat_layer_kernel(const __half* __restrict__ ewe,
                      const float* __restrict__ att,
                      const float* __restrict__ bias,
                      float* __restrict__ outbuf,
                      int doElu) {
    int lane = threadIdx.x & 31;
    int node = (blockIdx.x * blockDim.x + threadIdx.x) >> 5;
    if (node >= NN) return;

    float2 a2 = ((const float2*)att)[lane];
    float2 b2 = ((const float2*)bias)[lane];
    const float2* xlr2 = (const float2*)g_xlr;
    const __half2* ewe2 = (const __half2*)ewe;

    int start = g_rowptr[node], end = g_rowptr[node + 1];
    float2 rf  = xlr2[node * 64 + 32 + lane];
    float2 vSf = xlr2[node * 64 + lane];
    ull r2  = pack2(rf.x, rf.y);
    ull vS2 = pack2(vSf.x, vSf.y);

    float amax = -INFINITY, den = 0.f;
    ull acc = 0, wsum = 0;

    ull vA = 0, wA = 0, vB = 0, wB = 0;
    if (start < end) {
        int2 se = g_csr_se[start];
        float2 t = xlr2[se.x * 64 + lane];            vA = pack2(t.x, t.y);
        float2 u = __half22float2(ewe2[(size_t)se.y * 32 + lane]); wA = pack2(u.x, u.y);
    }
    if (start + 1 < end) {
        int2 se = g_csr_se[start + 1];
        float2 t = xlr2[se.x * 64 + lane];            vB = pack2(t.x, t.y);
        float2 u = __half22float2(ewe2[(size_t)se.y * 32 + lane]); wB = pack2(u.x, u.y);
    }

    int p = start;
    for (; p + 1 < end; p += 2) {
        ull v0 = vA, w0 = wA, v1 = vB, w1 = wB;
        if (p + 2 < end) {
            int2 se = g_csr_se[p + 2];
            float2 t = xlr2[se.x * 64 + lane];            vA = pack2(t.x, t.y);
            float2 u = __half22float2(ewe2[(size_t)se.y * 32 + lane]); wA = pack2(u.x, u.y);
        }
        if (p + 3 < end) {
            int2 se = g_csr_se[p + 3];
            float2 t = xlr2[se.x * 64 + lane];            vB = pack2(t.x, t.y);
            float2 u = __half22float2(ewe2[(size_t)se.y * 32 + lane]); wB = pack2(u.x, u.y);
        }
        wsum = add2(wsum, add2(w0, w1));
        ull m0 = add2(add2(v0, r2), w0);
        ull m1 = add2(add2(v1, r2), w1);
        float m0x, m0y, m1x, m1y;
        unpack2(m0, m0x, m0y);
        unpack2(m1, m1x, m1y);
        float pk0 = lrelu(m0x) * a2.x + lrelu(m0y) * a2.y;
        float pk1 = lrelu(m1x) * a2.x + lrelu(m1y) * a2.y;
        #pragma unroll
        for (int o = 16; o; o >>= 1) {
            pk0 += __shfl_xor_sync(0xffffffffu, pk0, o);
            pk1 += __shfl_xor_sync(0xffffffffu, pk1, o);
        }
        float pm = fmaxf(pk0, pk1);
        if (pm > amax) {
            float f = __expf(amax - pm);
            den *= f;
            acc = mul2(acc, pack2(f, f));
            amax = pm;
        }
        float e0 = __expf(pk0 - amax), e1 = __expf(pk1 - amax);
        den += e0 + e1;
        acc = ffma2(pack2(e0, e0), v0, acc);
        acc = ffma2(pack2(e1, e1), v1, acc);
    }
    if (p < end) {   // odd tail
        wsum = add2(wsum, wA);
        ull m0 = add2(add2(vA, r2), wA);
        float m0x, m0y;
        unpack2(m0, m0x, m0y);
        float pk0 = lrelu(m0x) * a2.x + lrelu(m0y) * a2.y;
        #pragma unroll
        for (int o = 16; o; o >>= 1) pk0 += __shfl_xor_sync(0xffffffffu, pk0, o);
        if (pk0 > amax) {
            float f = __expf(amax - pk0);
            den *= f;
            acc = mul2(acc, pack2(f, f));
            amax = pk0;
        }
        float e0 = __expf(pk0 - amax);
        den += e0;
        acc = ffma2(pack2(e0, e0), vA, acc);
    }

    // self loop: ewe_self = mean(ewe) over incoming edges (linearity of @We)
    float invdeg = 1.f / fmaxf((float)(end - start), 1.f);
    ull mS = add2(add2(vS2, r2), mul2(wsum, pack2(invdeg, invdeg)));
    float msx, msy;
    unpack2(mS, msx, msy);
    float pS = lrelu(msx) * a2.x + lrelu(msy) * a2.y;
    #pragma unroll
    for (int o = 16; o; o >>= 1) pS += __shfl_xor_sync(0xffffffffu, pS, o);
    if (pS > amax) {
        float f = __expf(amax - pS);
        den *= f;
        acc = mul2(acc, pack2(f, f));
        amax = pS;
    }
    float eS = __expf(pS - amax);
    den += eS;
    acc = ffma2(pack2(eS, eS), vS2, acc);

    float inv = 1.f / den;
    float accx, accy;
    unpack2(acc, accx, accy);
    float ox = accx * inv + b2.x;
    float oy = accy * inv + b2.y;
    if (doElu) { ox = eluf(ox); oy = eluf(oy); }
    ((float2*)outbuf)[node * 32 + lane] = make_float2(ox, oy);
}

// ---------------- edge classifier: warp per edge PAIR, fp16 weights ----------
__global__ __launch_bounds__(128)
void classifier_kernel(const float* __restrict__ eattr,
                       const int* __restrict__ ei,
                       const float* __restrict__ Cw1c,   // [16][256]
                       const float* __restrict__ Cb1,
                       const float* __restrict__ Cw2,
                       const float* __restrict__ Cb2,
                       float* __restrict__ out) {
    int lane = threadIdx.x & 31;
    int c0 = 4 * lane;
    __half2 wh[DE][4];
    #pragma unroll
    for (int k = 0; k < DE; k++) {
        float4 A = *(const float4*)&Cw1c[k * HID + c0];
        float4 B = *(const float4*)&Cw1c[k * HID + 128 + c0];
        wh[k][0] = __floats2half2_rn(A.x, A.y);
        wh[k][1] = __floats2half2_rn(A.z, A.w);
        wh[k][2] = __floats2half2_rn(B.x, B.y);
        wh[k][3] = __floats2half2_rn(B.z, B.w);
    }
    float4 b0 = *(const float4*)&Cb1[c0];
    float4 b1 = *(const float4*)&Cb1[128 + c0];
    float4 c20 = *(const float4*)&Cw2[c0];
    float4 c21 = *(const float4*)&Cw2[128 + c0];
    float cb2 = Cb2[0];

    const float4* P  = (const float4*)g_P12;
    const float4* EA = (const float4*)eattr;
    int pairGid = (blockIdx.x * blockDim.x + threadIdx.x) >> 5;
    int pairsTotal = (gridDim.x * blockDim.x) >> 5;
    const int NPAIR = EE / 2;

    for (int pr = pairGid; pr < NPAIR; pr += pairsTotal) {
        int e0 = 2 * pr, e1 = 2 * pr + 1;
        int src0 = ei[e0], dst0 = ei[EE + e0];
        int src1 = ei[e1], dst1 = ei[EE + e1];
        float4 p1a0 = P[(size_t)src0 * 128 + lane];
        float4 p1b0 = P[(size_t)src0 * 128 + 32 + lane];
        float4 p2a0 = P[(size_t)dst0 * 128 + 64 + lane];
        float4 p2b0 = P[(size_t)dst0 * 128 + 96 + lane];
        float4 p1a1 = P[(size_t)src1 * 128 + lane];
        float4 p1b1 = P[(size_t)src1 * 128 + 32 + lane];
        float4 p2a1 = P[(size_t)dst1 * 128 + 64 + lane];
        float4 p2b1 = P[(size_t)dst1 * 128 + 96 + lane];
        __half2 x0 = __float2half2_rn(0.f), x1 = x0, x2 = x0, x3 = x0;
        __half2 y0 = x0, y1 = x0, y2 = x0, y3 = x0;
        #pragma unroll
        for (int kq = 0; kq < 4; kq++) {
            float4 ea0 = EA[(size_t)e0 * 4 + kq];
            float4 ea1 = EA[(size_t)e1 * 4 + kq];
            const float* e0p = (const float*)&ea0;
            const float* e1p = (const float*)&ea1;
            #pragma unroll
            for (int j = 0; j < 4; j++) {
                int k = kq * 4 + j;
                __half2 s0 = __float2half2_rn(e0p[j]);
                __half2 s1 = __float2half2_rn(e1p[j]);
                x0 = __hfma2(s0, wh[k][0], x0);
                x1 = __hfma2(s0, wh[k][1], x1);
                x2 = __hfma2(s0, wh[k][2], x2);
                x3 = __hfma2(s0, wh[k][3], x3);
                y0 = __hfma2(s1, wh[k][0], y0);
                y1 = __hfma2(s1, wh[k][1], y1);
                y2 = __hfma2(s1, wh[k][2], y2);
                y3 = __hfma2(s1, wh[k][3], y3);
            }
        }
        float2 f0 = __half22float2(x0), f1 = __half22float2(x1);
        float2 f2 = __half22float2(x2), f3 = __half22float2(x3);
        float2 g0 = __half22float2(y0), g1 = __half22float2(y1);
        float2 g2 = __half22float2(y2), g3 = __half22float2(y3);
        float acc0 =
              eluf(f0.x + p1a0.x + p2a0.x + b0.x) * c20.x
            + eluf(f0.y + p1a0.y + p2a0.y + b0.y) * c20.y
            + eluf(f1.x + p1a0.z + p2a0.z + b0.z) * c20.z
            + eluf(f1.y + p1a0.w + p2a0.w + b0.w) * c20.w
            + eluf(f2.x + p1b0.x + p2b0.x + b1.x) * c21.x
            + eluf(f2.y + p1b0.y + p2b0.y + b1.y) * c21.y
            + eluf(f3.x + p1b0.z + p2b0.z + b1.z) * c21.z
            + eluf(f3.y + p1b0.w + p2b0.w + b1.w) * c21.w;
        float acc1 =
              eluf(g0.x + p1a1.x + p2a1.x + b0.x) * c20.x
            + eluf(g0.y + p1a1.y + p2a1.y + b0.y) * c20.y
            + eluf(g1.x + p1a1.z + p2a1.z + b0.z) * c20.z
            + eluf(g1.y + p1a1.w + p2a1.w + b0.w) * c20.w
            + eluf(g2.x + p1b1.x + p2b1.x + b1.x) * c21.x
            + eluf(g2.y + p1b1.y + p2b1.y + b1.y) * c21.y
            + eluf(g3.x + p1b1.z + p2b1.z + b1.z) * c21.z
            + eluf(g3.y + p1b1.w + p2b1.w + b1.w) * c21.w;
        #pragma unroll
        for (int o = 16; o; o >>= 1) {
            acc0 += __shfl_xor_sync(0xffffffffu, acc0, o);
            acc1 += __shfl_xor_sync(0xffffffffu, acc1, o);
        }
        if (lane == 0) {
            out[e0] = acc0 + cb2;
            out[e1] = acc1 + cb2;
        }
    }
}

// ---------------- host orchestration ----------------------------------------
static inline int ceil_div(int a, int b) { return (a + b - 1) / b; }

extern "C" void kernel_launch(void* const* d_in, const int* in_sizes, int n_in,
                              void* d_out, int out_size) {
    const float* x     = (const float*)d_in[0];
    const float* eattr = (const float*)d_in[1];
    const float* W1l   = (const float*)d_in[2];
    const float* b1l   = (const float*)d_in[3];
    const float* W1r   = (const float*)d_in[4];
    const float* b1r   = (const float*)d_in[5];
    const float* We1   = (const float*)d_in[6];
    const float* att1  = (const float*)d_in[7];
    const float* bias1 = (const float*)d_in[8];
    const float* W2l   = (const float*)d_in[9];
    const float* b2l   = (const float*)d_in[10];
    const float* W2r   = (const float*)d_in[11];
    const float* b2r   = (const float*)d_in[12];
    const float* We2   = (const float*)d_in[13];
    const float* att2  = (const float*)d_in[14];
    const float* bias2 = (const float*)d_in[15];
    // d_in[16..19] (Aw1/Ab1/Aw2/Ab2): softmax over a single column == 1 -> unused
    const float* Cw1   = (const float*)d_in[20];
    const float* Cb1   = (const float*)d_in[21];
    const float* Cw2   = (const float*)d_in[22];
    const float* Cb2   = (const float*)d_in[23];
    const int*   ei    = (const int*)  d_in[24];
    float* out = (float*)d_out;

    float *d_h, *d_h2, *d_P12, *d_Wp2, *d_WpC, *d_bp2, *d_xlr;
    __half *d_ewe1, *d_ewe2;
    cudaGetSymbolAddress((void**)&d_h,    g_h);
    cudaGetSymbolAddress((void**)&d_h2,   g_h2);
    cudaGetSymbolAddress((void**)&d_P12,  g_P12);
    cudaGetSymbolAddress((void**)&d_Wp2,  g_Wp2);
    cudaGetSymbolAddress((void**)&d_WpC,  g_WpC);
    cudaGetSymbolAddress((void**)&d_bp2,  g_bp2);
    cudaGetSymbolAddress((void**)&d_xlr,  g_xlr);
    cudaGetSymbolAddress((void**)&d_ewe1, g_ewe1);
    cudaGetSymbolAddress((void**)&d_ewe2, g_ewe2);

    const int TB = 256;
    int gatBlocks = ceil_div(NN * 32, TB);

    // 1: pack weights + histogram
    prep_kernel<<<ceil_div(EE, TB), TB>>>(W1l, W1r, b1l, b1r, W2l, W2r, b2l, b2r,
                                          We1, We2, Cw1, ei);
    // 2: scan (+ re-zero g_cnt)
    csr_scan_kernel<<<1, 1024>>>();
    // 3: CSR scatter + layer-1 GEMM fused
    scatter_gemm_kernel<<<SCAT_BLOCKS + 2 * ROW_BLOCKS, 256>>>(ei, x);
    // 4: ewe GEMM standalone  (ncu capture slot)
    ewe_kernel<<<EWE_BLOCKS, 256>>>(eattr);
    // 5: GAT layer 1
    gat_layer_kernel<<<gatBlocks, TB>>>(d_ewe1, att1, bias1, d_h, 1);
    // 6-7: layer 2
    gemm_tf32_kernel<<<dim3(ROW_BLOCKS, 2), 256>>>(d_h, d_Wp2, d_bp2, d_xlr, NN, C, 128);
    gat_layer_kernel<<<gatBlocks, TB>>>(d_ewe2, att2, bias2, d_h2, 0);
    // 8-9: classifier
    gemm_tf32_kernel<<<dim3(ROW_BLOCKS, 8), 256>>>(d_h2, d_WpC, nullptr, d_P12, NN, C, 512);
    classifier_kernel<<<2368, 128>>>(eattr, ei, Cw1 + 2 * C * HID, Cb1, Cw2, Cb2, out);
}